// round 6
// baseline (speedup 1.0000x reference)
#include <cuda_runtime.h>
#include <cuda_fp16.h>

#define NN 50000
#define NE 1600000
#define DD 32
static constexpr float Hstep = 0.1f;

// ---------------- static device scratch ----------------
__device__ int   g_is64;
__device__ int   g_deg[NN];
__device__ int   g_cur[NN];
__device__ int   g_rowptr[2][NN + 1];
__device__ __align__(16) int2  g_colval[2][NE];
__device__ float g_dis[2][NN];
__device__ __align__(16) __half g_tmph[2][NN * DD];  // ping-pong (y @ W), fp16
__device__ __align__(128) float g_x[NN * DD];
__device__ __align__(128) float g_ksum[NN * DD];

// ---------------- edge readers (dtype-agnostic) ----------------
__device__ __forceinline__ int edge_src(const void* ei, int e, int is64) {
    if (is64) return (int)((const long long*)ei)[e];
    return ((const int*)ei)[e];
}
__device__ __forceinline__ int edge_dst(const void* ei, int e, int is64) {
    if (is64) return (int)((const long long*)ei)[NE + e];
    return ((const int*)ei)[NE + e];
}

// ---------------- setup: probe dtype + zero degree ----------------
__global__ void k_probe_zero(const int* __restrict__ w) {
    if (blockIdx.x == 0) {
        __shared__ int anynz;
        if (threadIdx.x == 0) anynz = 0;
        __syncthreads();
        // int64 little-endian: odd words of first 256 elements are all 0 (< 50000)
        if (w[2 * threadIdx.x + 1] != 0) atomicOr(&anynz, 1);
        __syncthreads();
        if (threadIdx.x == 0) g_is64 = (anynz == 0) ? 1 : 0;
    }
    int i = blockIdx.x * blockDim.x + threadIdx.x;
    int stride = gridDim.x * blockDim.x;
    for (; i < NN; i += stride) g_deg[i] = 0;
}

__global__ void k_hist(const void* __restrict__ ei) {
    const int is64 = g_is64;
    int stride = gridDim.x * blockDim.x;
    for (int e = blockIdx.x * blockDim.x + threadIdx.x; e < NE; e += stride) {
        int d = edge_dst(ei, e, is64);
        atomicAdd(&g_deg[d], 1);
    }
}

// dis = rsqrt(deg+1); exclusive scan of deg -> rowptr, cur. One block.
__global__ void k_scan_dis(int b) {
    __shared__ int sm[1024];
    const int tid = threadIdx.x;
    const int CH = (NN + 1023) / 1024;  // 49
    int base = tid * CH;
    int s = 0;
    for (int i = 0; i < CH; i++) {
        int idx = base + i;
        if (idx < NN) {
            int d = g_deg[idx];
            g_dis[b][idx] = rsqrtf((float)d + 1.0f);
            s += d;
        }
    }
    sm[tid] = s;
    __syncthreads();
    for (int off = 1; off < 1024; off <<= 1) {
        int v = (tid >= off) ? sm[tid - off] : 0;
        __syncthreads();
        sm[tid] += v;
        __syncthreads();
    }
    int run = (tid == 0) ? 0 : sm[tid - 1];
    for (int i = 0; i < CH; i++) {
        int idx = base + i;
        if (idx < NN) {
            g_rowptr[b][idx] = run;
            g_cur[idx] = run;
            run += g_deg[idx];
        }
    }
    if (tid == 1023) g_rowptr[b][NN] = sm[1023];
}

// blocks [0,EB): scatter edges into CSR; blocks [EB,..): g_x=x0, tmph[0]=x0@W
__global__ void __launch_bounds__(256) k_scatter_init(
    const void* __restrict__ ei, int b, int EB,
    const float* __restrict__ x0, const float* __restrict__ W) {
    if (blockIdx.x < EB) {
        const int is64 = g_is64;
        int stride = EB * blockDim.x;
        for (int e = blockIdx.x * blockDim.x + threadIdx.x; e < NE; e += stride) {
            int s = edge_src(ei, e, is64);
            int d = edge_dst(ei, e, is64);
            int p = atomicAdd(&g_cur[d], 1);
            int2 cv;
            cv.x = s;
            cv.y = __float_as_int(g_dis[b][s] * g_dis[b][d]);
            g_colval[b][p] = cv;
        }
    } else {
        const int lane = threadIdx.x & 31;
        float Wc[32];
#pragma unroll
        for (int d = 0; d < 32; d++) Wc[d] = __ldg(&W[d * 32 + lane]);
        int warpId = ((blockIdx.x - EB) * blockDim.x + threadIdx.x) >> 5;
        int nw = ((gridDim.x - EB) * blockDim.x) >> 5;
        for (int r = warpId; r < NN; r += nw) {
            float xv = x0[r * 32 + lane];
            g_x[r * 32 + lane] = xv;
            float o = 0.f;
#pragma unroll
            for (int d = 0; d < 32; d++)
                o += __shfl_sync(0xffffffffu, xv, d) * Wc[d];
            g_tmph[0][r * 32 + lane] = __float2half(o);
        }
    }
}

// ---------------- fused RK4 stage: warp per row ----------------
// 4 groups of 8 lanes take every-4th edge of the SAME row; lane li owns dims
// li*4..li*4+3 (half2x2 = 8B gather per lane). Partial sums combined with
// shfl_xor(8,16). Epilogue applies @W via shuffles from group 0.
template <int STAGE>
__global__ void __launch_bounds__(256, 3) k_stage(
    int pin, int b,
    const float* __restrict__ W, const float* __restrict__ bvec,
    const float* __restrict__ wt, float t, float* __restrict__ xout) {
    const __half* __restrict__ tin = g_tmph[pin];
    __half* __restrict__ tout = g_tmph[pin ^ 1];
    const uint2* __restrict__ tin_v = (const uint2*)tin;   // 8 uint2 per row
    const int2* __restrict__ colval = g_colval[b];
    const int* __restrict__ rowptr = g_rowptr[b];
    const float* __restrict__ dis = g_dis[b];

    const int lane = threadIdx.x & 31;
    const int li = lane & 7;      // lane within 8-lane group
    const int g = lane >> 3;      // group id (edge phase)

    float Wc[32];
#pragma unroll
    for (int d = 0; d < 32; d++) Wc[d] = __ldg(&W[d * 32 + lane]);
    const float4 bb = *(const float4*)(bvec + li * 4);
    const float4 wl = *(const float4*)(wt + li * 4);
    float4 gate;
    gate.x = 1.0f / (1.0f + __expf(-t * wl.x));
    gate.y = 1.0f / (1.0f + __expf(-t * wl.y));
    gate.z = 1.0f / (1.0f + __expf(-t * wl.z));
    gate.w = 1.0f / (1.0f + __expf(-t * wl.w));

    int warpId = (blockIdx.x * blockDim.x + threadIdx.x) >> 5;
    int nw = (gridDim.x * blockDim.x) >> 5;

    for (int r = warpId; r < NN; r += nw) {
        const int st = rowptr[r];
        const int en = rowptr[r + 1];
        float4 acc = make_float4(0.f, 0.f, 0.f, 0.f);
        for (int e = st + g; e < en; e += 4) {
            const int2 cv = __ldg(&colval[e]);
            const float v = __int_as_float(cv.y);
            union { uint2 u; __half2 h[2]; } rw;
            rw.u = __ldg(&tin_v[(size_t)cv.x * 8 + li]);
            const float2 a01 = __half22float2(rw.h[0]);
            const float2 a23 = __half22float2(rw.h[1]);
            acc.x += v * a01.x;
            acc.y += v * a01.y;
            acc.z += v * a23.x;
            acc.w += v * a23.y;
        }
        // combine the 4 groups' partial sums (lanes with equal li)
#pragma unroll
        for (int off = 8; off < 32; off <<= 1) {
            acc.x += __shfl_xor_sync(0xffffffffu, acc.x, off);
            acc.y += __shfl_xor_sync(0xffffffffu, acc.y, off);
            acc.z += __shfl_xor_sync(0xffffffffu, acc.z, off);
            acc.w += __shfl_xor_sync(0xffffffffu, acc.w, off);
        }

        const float dn = dis[r];
        const float sn = dn * dn;
        union { uint2 u; __half2 h[2]; } sw;
        sw.u = __ldg(&tin_v[(size_t)r * 8 + li]);
        const float2 s01 = __half22float2(sw.h[0]);
        const float2 s23 = __half22float2(sw.h[1]);

        float4 k4;
        k4.x = fmaxf(acc.x + sn * s01.x + bb.x, 0.f) * gate.x;
        k4.y = fmaxf(acc.y + sn * s01.y + bb.y, 0.f) * gate.y;
        k4.z = fmaxf(acc.z + sn * s23.x + bb.z, 0.f) * gate.z;
        k4.w = fmaxf(acc.w + sn * s23.y + bb.w, 0.f) * gate.w;

        const float4 xv = *(const float4*)(g_x + (size_t)r * 32 + li * 4);
        float4* ksp = (float4*)(g_ksum + (size_t)r * 32 + li * 4);
        float4 y;
        if (STAGE == 1) {
            if (g == 0) *ksp = k4;
            y.x = xv.x + 0.5f * Hstep * k4.x;
            y.y = xv.y + 0.5f * Hstep * k4.y;
            y.z = xv.z + 0.5f * Hstep * k4.z;
            y.w = xv.w + 0.5f * Hstep * k4.w;
        } else if (STAGE == 2) {
            float4 ks = *ksp;
            ks.x += 2.f * k4.x; ks.y += 2.f * k4.y;
            ks.z += 2.f * k4.z; ks.w += 2.f * k4.w;
            if (g == 0) *ksp = ks;
            y.x = xv.x + 0.5f * Hstep * k4.x;
            y.y = xv.y + 0.5f * Hstep * k4.y;
            y.z = xv.z + 0.5f * Hstep * k4.z;
            y.w = xv.w + 0.5f * Hstep * k4.w;
        } else if (STAGE == 3) {
            float4 ks = *ksp;
            ks.x += 2.f * k4.x; ks.y += 2.f * k4.y;
            ks.z += 2.f * k4.z; ks.w += 2.f * k4.w;
            if (g == 0) *ksp = ks;
            y.x = xv.x + Hstep * k4.x;
            y.y = xv.y + Hstep * k4.y;
            y.z = xv.z + Hstep * k4.z;
            y.w = xv.w + Hstep * k4.w;
        } else {
            const float4 ks = *ksp;
            y.x = xv.x + (Hstep / 6.f) * (ks.x + k4.x);
            y.y = xv.y + (Hstep / 6.f) * (ks.y + k4.y);
            y.z = xv.z + (Hstep / 6.f) * (ks.z + k4.z);
            y.w = xv.w + (Hstep / 6.f) * (ks.w + k4.w);
            if (g == 0) {
                if (xout) *(float4*)(xout + (size_t)r * 32 + li * 4) = y;
                else      *(float4*)(g_x + (size_t)r * 32 + li * 4) = y;
            }
        }

        // Epilogue: tout[r] = y @ W. Dim d=4*dq+c lives in lane dq (group 0), comp c.
        float o = 0.f;
#pragma unroll
        for (int dq = 0; dq < 8; dq++) {
            o += __shfl_sync(0xffffffffu, y.x, dq) * Wc[4 * dq + 0];
            o += __shfl_sync(0xffffffffu, y.y, dq) * Wc[4 * dq + 1];
            o += __shfl_sync(0xffffffffu, y.z, dq) * Wc[4 * dq + 2];
            o += __shfl_sync(0xffffffffu, y.w, dq) * Wc[4 * dq + 3];
        }
        tout[(size_t)r * 32 + lane] = __float2half(o);
    }
}

// ---------------- host ----------------
extern "C" void kernel_launch(void* const* d_in, const int* in_sizes, int n_in,
                              void* d_out, int out_size) {
    const float* x0 = (const float*)d_in[0];
    const void* epos = d_in[1];
    const void* eneg = d_in[2];
    const float* Wp = (const float*)d_in[3];
    const float* bp = (const float*)d_in[4];
    const float* wtp = (const float*)d_in[5];
    const float* Wn = (const float*)d_in[6];
    const float* bn = (const float*)d_in[7];
    const float* wtn = (const float*)d_in[8];
    float* out = (float*)d_out;

    const int SPMM_BLOCKS = 444;   // 3 blocks/SM x 148 SMs
    const int EDGE_BLOCKS = 1184;
    const int INIT_BLOCKS = 444;

    for (int b = 0; b < 2; b++) {
        const void* ei = b ? eneg : epos;
        const float* W = b ? Wn : Wp;
        const float* bv = b ? bn : bp;
        const float* wt = b ? wtn : wtp;

        k_probe_zero<<<196, 256>>>((const int*)epos);
        k_hist<<<EDGE_BLOCKS, 256>>>(ei);
        k_scan_dis<<<1, 1024>>>(b);
        k_scatter_init<<<EDGE_BLOCKS + INIT_BLOCKS, 256>>>(ei, b, EDGE_BLOCKS, x0, W);

        int pin = 0;
        for (int step = 0; step < 10; step++) {
            float t = step * Hstep;
            k_stage<1><<<SPMM_BLOCKS, 256>>>(pin, b, W, bv, wt, t, nullptr);
            pin ^= 1;
            k_stage<2><<<SPMM_BLOCKS, 256>>>(pin, b, W, bv, wt, t + 0.5f * Hstep, nullptr);
            pin ^= 1;
            k_stage<3><<<SPMM_BLOCKS, 256>>>(pin, b, W, bv, wt, t + 0.5f * Hstep, nullptr);
            pin ^= 1;
            float* xo = (step == 9) ? (out + (size_t)b * NN * DD) : nullptr;
            k_stage<4><<<SPMM_BLOCKS, 256>>>(pin, b, W, bv, wt, t + Hstep, xo);
            pin ^= 1;
        }
    }
}

// round 7
// speedup vs baseline: 1.0564x; 1.0564x over previous
#include <cuda_runtime.h>
#include <cuda_fp16.h>

#define NN 50000
#define NE 1600000
#define DD 32
static constexpr float Hstep = 0.1f;

// ---------------- static device scratch ----------------
__device__ int   g_is64;
__device__ int   g_deg[NN];
__device__ int   g_cur[NN];
__device__ int   g_rowptr[2][NN + 1];
__device__ __align__(16) int2  g_colval[2][NE];
__device__ float g_dis[2][NN];
__device__ __align__(16) __half g_tmph[2][NN * DD];  // ping-pong (y @ W), fp16
__device__ __align__(128) float g_x[NN * DD];
__device__ __align__(128) float g_ksum[NN * DD];

// ---------------- edge readers (dtype-agnostic) ----------------
__device__ __forceinline__ int edge_src(const void* ei, int e, int is64) {
    if (is64) return (int)((const long long*)ei)[e];
    return ((const int*)ei)[e];
}
__device__ __forceinline__ int edge_dst(const void* ei, int e, int is64) {
    if (is64) return (int)((const long long*)ei)[NE + e];
    return ((const int*)ei)[NE + e];
}

// ---------------- setup: probe dtype + zero degree ----------------
__global__ void k_probe_zero(const int* __restrict__ w) {
    if (blockIdx.x == 0) {
        __shared__ int anynz;
        if (threadIdx.x == 0) anynz = 0;
        __syncthreads();
        if (w[2 * threadIdx.x + 1] != 0) atomicOr(&anynz, 1);
        __syncthreads();
        if (threadIdx.x == 0) g_is64 = (anynz == 0) ? 1 : 0;
    }
    int i = blockIdx.x * blockDim.x + threadIdx.x;
    int stride = gridDim.x * blockDim.x;
    for (; i < NN; i += stride) g_deg[i] = 0;
}

__global__ void k_hist(const void* __restrict__ ei) {
    const int is64 = g_is64;
    int stride = gridDim.x * blockDim.x;
    for (int e = blockIdx.x * blockDim.x + threadIdx.x; e < NE; e += stride) {
        int d = edge_dst(ei, e, is64);
        atomicAdd(&g_deg[d], 1);
    }
}

// dis = rsqrt(deg+1); exclusive scan of deg -> rowptr, cur. One block.
__global__ void k_scan_dis(int b) {
    __shared__ int sm[1024];
    const int tid = threadIdx.x;
    const int CH = (NN + 1023) / 1024;  // 49
    int base = tid * CH;
    int s = 0;
    for (int i = 0; i < CH; i++) {
        int idx = base + i;
        if (idx < NN) {
            int d = g_deg[idx];
            g_dis[b][idx] = rsqrtf((float)d + 1.0f);
            s += d;
        }
    }
    sm[tid] = s;
    __syncthreads();
    for (int off = 1; off < 1024; off <<= 1) {
        int v = (tid >= off) ? sm[tid - off] : 0;
        __syncthreads();
        sm[tid] += v;
        __syncthreads();
    }
    int run = (tid == 0) ? 0 : sm[tid - 1];
    for (int i = 0; i < CH; i++) {
        int idx = base + i;
        if (idx < NN) {
            g_rowptr[b][idx] = run;
            g_cur[idx] = run;
            run += g_deg[idx];
        }
    }
    if (tid == 1023) g_rowptr[b][NN] = sm[1023];
}

// blocks [0,EB): scatter edges into CSR; blocks [EB,..): g_x=x0, tmph[0]=x0@W
__global__ void __launch_bounds__(256) k_scatter_init(
    const void* __restrict__ ei, int b, int EB,
    const float* __restrict__ x0, const float* __restrict__ W) {
    if (blockIdx.x < EB) {
        const int is64 = g_is64;
        int stride = EB * blockDim.x;
        for (int e = blockIdx.x * blockDim.x + threadIdx.x; e < NE; e += stride) {
            int s = edge_src(ei, e, is64);
            int d = edge_dst(ei, e, is64);
            int p = atomicAdd(&g_cur[d], 1);
            int2 cv;
            cv.x = s;
            cv.y = __float_as_int(g_dis[b][s] * g_dis[b][d]);
            g_colval[b][p] = cv;
        }
    } else {
        const int lane = threadIdx.x & 31;
        float Wc[32];
#pragma unroll
        for (int d = 0; d < 32; d++) Wc[d] = __ldg(&W[d * 32 + lane]);
        int warpId = ((blockIdx.x - EB) * blockDim.x + threadIdx.x) >> 5;
        int nw = ((gridDim.x - EB) * blockDim.x) >> 5;
        for (int r = warpId; r < NN; r += nw) {
            float xv = x0[r * 32 + lane];
            g_x[r * 32 + lane] = xv;
            float o = 0.f;
#pragma unroll
            for (int d = 0; d < 32; d++)
                o += __shfl_sync(0xffffffffu, xv, d) * Wc[d];
            g_tmph[0][r * 32 + lane] = __float2half(o);
        }
    }
}

// ---------------- fused RK4 stage: warp per row, batch-4 pipelined gather ----
template <int STAGE>
__global__ void __launch_bounds__(256, 4) k_stage(
    int pin, int b,
    const float* __restrict__ W, const float* __restrict__ bvec,
    const float* __restrict__ wt, float t, float* __restrict__ xout) {
    const __half* __restrict__ tin = g_tmph[pin];
    __half* __restrict__ tout = g_tmph[pin ^ 1];
    const uint2* __restrict__ tin_v = (const uint2*)tin;   // 8 uint2 per row
    const int2* __restrict__ colval = g_colval[b];
    const int* __restrict__ rowptr = g_rowptr[b];
    const float* __restrict__ dis = g_dis[b];

    __shared__ float Ws[DD * DD];
    {
        int tid = threadIdx.x;
#pragma unroll
        for (int j = 0; j < 4; j++) Ws[tid * 4 + j] = W[tid * 4 + j];
    }
    __syncthreads();

    const int lane = threadIdx.x & 31;
    const int li = lane & 7;      // lane within 8-lane group
    const int g = lane >> 3;      // group id (edge phase)

    const float4 bb = *(const float4*)(bvec + li * 4);
    const float4 wl = *(const float4*)(wt + li * 4);
    float4 gate;
    gate.x = 1.0f / (1.0f + __expf(-t * wl.x));
    gate.y = 1.0f / (1.0f + __expf(-t * wl.y));
    gate.z = 1.0f / (1.0f + __expf(-t * wl.z));
    gate.w = 1.0f / (1.0f + __expf(-t * wl.w));

    int warpId = (blockIdx.x * blockDim.x + threadIdx.x) >> 5;
    int nw = (gridDim.x * blockDim.x) >> 5;

    for (int r = warpId; r < NN; r += nw) {
        const int st = rowptr[r];
        const int en = rowptr[r + 1];
        float4 acc = make_float4(0.f, 0.f, 0.f, 0.f);

        int e = st + g;
        // batch of 4 edges per group: MLP-4 colval loads, then MLP-4 gathers
        for (; e + 12 < en; e += 16) {
            const int2 c0 = __ldg(&colval[e]);
            const int2 c1 = __ldg(&colval[e + 4]);
            const int2 c2 = __ldg(&colval[e + 8]);
            const int2 c3 = __ldg(&colval[e + 12]);
            union { uint2 u; __half2 h[2]; } r0, r1, r2, r3;
            r0.u = __ldg(&tin_v[(size_t)c0.x * 8 + li]);
            r1.u = __ldg(&tin_v[(size_t)c1.x * 8 + li]);
            r2.u = __ldg(&tin_v[(size_t)c2.x * 8 + li]);
            r3.u = __ldg(&tin_v[(size_t)c3.x * 8 + li]);
            float v;
            float2 a;
            v = __int_as_float(c0.y);
            a = __half22float2(r0.h[0]); acc.x += v * a.x; acc.y += v * a.y;
            a = __half22float2(r0.h[1]); acc.z += v * a.x; acc.w += v * a.y;
            v = __int_as_float(c1.y);
            a = __half22float2(r1.h[0]); acc.x += v * a.x; acc.y += v * a.y;
            a = __half22float2(r1.h[1]); acc.z += v * a.x; acc.w += v * a.y;
            v = __int_as_float(c2.y);
            a = __half22float2(r2.h[0]); acc.x += v * a.x; acc.y += v * a.y;
            a = __half22float2(r2.h[1]); acc.z += v * a.x; acc.w += v * a.y;
            v = __int_as_float(c3.y);
            a = __half22float2(r3.h[0]); acc.x += v * a.x; acc.y += v * a.y;
            a = __half22float2(r3.h[1]); acc.z += v * a.x; acc.w += v * a.y;
        }
        for (; e < en; e += 4) {
            const int2 cv = __ldg(&colval[e]);
            const float v = __int_as_float(cv.y);
            union { uint2 u; __half2 h[2]; } rw;
            rw.u = __ldg(&tin_v[(size_t)cv.x * 8 + li]);
            const float2 a01 = __half22float2(rw.h[0]);
            const float2 a23 = __half22float2(rw.h[1]);
            acc.x += v * a01.x;
            acc.y += v * a01.y;
            acc.z += v * a23.x;
            acc.w += v * a23.y;
        }
        // combine the 4 groups' partial sums (lanes with equal li)
#pragma unroll
        for (int off = 8; off < 32; off <<= 1) {
            acc.x += __shfl_xor_sync(0xffffffffu, acc.x, off);
            acc.y += __shfl_xor_sync(0xffffffffu, acc.y, off);
            acc.z += __shfl_xor_sync(0xffffffffu, acc.z, off);
            acc.w += __shfl_xor_sync(0xffffffffu, acc.w, off);
        }

        const float dn = dis[r];
        const float sn = dn * dn;
        union { uint2 u; __half2 h[2]; } sw;
        sw.u = __ldg(&tin_v[(size_t)r * 8 + li]);
        const float2 s01 = __half22float2(sw.h[0]);
        const float2 s23 = __half22float2(sw.h[1]);

        float4 k4;
        k4.x = fmaxf(acc.x + sn * s01.x + bb.x, 0.f) * gate.x;
        k4.y = fmaxf(acc.y + sn * s01.y + bb.y, 0.f) * gate.y;
        k4.z = fmaxf(acc.z + sn * s23.x + bb.z, 0.f) * gate.z;
        k4.w = fmaxf(acc.w + sn * s23.y + bb.w, 0.f) * gate.w;

        const float4 xv = *(const float4*)(g_x + (size_t)r * 32 + li * 4);
        float4* ksp = (float4*)(g_ksum + (size_t)r * 32 + li * 4);
        float4 y;
        if (STAGE == 1) {
            if (g == 0) *ksp = k4;
            y.x = xv.x + 0.5f * Hstep * k4.x;
            y.y = xv.y + 0.5f * Hstep * k4.y;
            y.z = xv.z + 0.5f * Hstep * k4.z;
            y.w = xv.w + 0.5f * Hstep * k4.w;
        } else if (STAGE == 2) {
            float4 ks = *ksp;
            ks.x += 2.f * k4.x; ks.y += 2.f * k4.y;
            ks.z += 2.f * k4.z; ks.w += 2.f * k4.w;
            if (g == 0) *ksp = ks;
            y.x = xv.x + 0.5f * Hstep * k4.x;
            y.y = xv.y + 0.5f * Hstep * k4.y;
            y.z = xv.z + 0.5f * Hstep * k4.z;
            y.w = xv.w + 0.5f * Hstep * k4.w;
        } else if (STAGE == 3) {
            float4 ks = *ksp;
            ks.x += 2.f * k4.x; ks.y += 2.f * k4.y;
            ks.z += 2.f * k4.z; ks.w += 2.f * k4.w;
            if (g == 0) *ksp = ks;
            y.x = xv.x + Hstep * k4.x;
            y.y = xv.y + Hstep * k4.y;
            y.z = xv.z + Hstep * k4.z;
            y.w = xv.w + Hstep * k4.w;
        } else {
            const float4 ks = *ksp;
            y.x = xv.x + (Hstep / 6.f) * (ks.x + k4.x);
            y.y = xv.y + (Hstep / 6.f) * (ks.y + k4.y);
            y.z = xv.z + (Hstep / 6.f) * (ks.z + k4.z);
            y.w = xv.w + (Hstep / 6.f) * (ks.w + k4.w);
            if (g == 0) {
                if (xout) *(float4*)(xout + (size_t)r * 32 + li * 4) = y;
                else      *(float4*)(g_x + (size_t)r * 32 + li * 4) = y;
            }
        }

        // Epilogue: tout[r] = y @ W (shuffles from lanes 0..7; W in smem)
        float o = 0.f;
#pragma unroll
        for (int dq = 0; dq < 8; dq++) {
            o += __shfl_sync(0xffffffffu, y.x, dq) * Ws[(4 * dq + 0) * 32 + lane];
            o += __shfl_sync(0xffffffffu, y.y, dq) * Ws[(4 * dq + 1) * 32 + lane];
            o += __shfl_sync(0xffffffffu, y.z, dq) * Ws[(4 * dq + 2) * 32 + lane];
            o += __shfl_sync(0xffffffffu, y.w, dq) * Ws[(4 * dq + 3) * 32 + lane];
        }
        tout[(size_t)r * 32 + lane] = __float2half(o);
    }
}

// ---------------- host ----------------
extern "C" void kernel_launch(void* const* d_in, const int* in_sizes, int n_in,
                              void* d_out, int out_size) {
    const float* x0 = (const float*)d_in[0];
    const void* epos = d_in[1];
    const void* eneg = d_in[2];
    const float* Wp = (const float*)d_in[3];
    const float* bp = (const float*)d_in[4];
    const float* wtp = (const float*)d_in[5];
    const float* Wn = (const float*)d_in[6];
    const float* bn = (const float*)d_in[7];
    const float* wtn = (const float*)d_in[8];
    float* out = (float*)d_out;

    const int SPMM_BLOCKS = 592;   // 4 blocks/SM x 148 SMs
    const int EDGE_BLOCKS = 1184;
    const int INIT_BLOCKS = 444;

    for (int b = 0; b < 2; b++) {
        const void* ei = b ? eneg : epos;
        const float* W = b ? Wn : Wp;
        const float* bv = b ? bn : bp;
        const float* wt = b ? wtn : wtp;

        k_probe_zero<<<196, 256>>>((const int*)epos);
        k_hist<<<EDGE_BLOCKS, 256>>>(ei);
        k_scan_dis<<<1, 1024>>>(b);
        k_scatter_init<<<EDGE_BLOCKS + INIT_BLOCKS, 256>>>(ei, b, EDGE_BLOCKS, x0, W);

        int pin = 0;
        for (int step = 0; step < 10; step++) {
            float t = step * Hstep;
            k_stage<1><<<SPMM_BLOCKS, 256>>>(pin, b, W, bv, wt, t, nullptr);
            pin ^= 1;
            k_stage<2><<<SPMM_BLOCKS, 256>>>(pin, b, W, bv, wt, t + 0.5f * Hstep, nullptr);
            pin ^= 1;
            k_stage<3><<<SPMM_BLOCKS, 256>>>(pin, b, W, bv, wt, t + 0.5f * Hstep, nullptr);
            pin ^= 1;
            float* xo = (step == 9) ? (out + (size_t)b * NN * DD) : nullptr;
            k_stage<4><<<SPMM_BLOCKS, 256>>>(pin, b, W, bv, wt, t + Hstep, xo);
            pin ^= 1;
        }
    }
}

// round 11
// speedup vs baseline: 1.2008x; 1.1367x over previous
#include <cuda_runtime.h>
#include <cuda_fp16.h>

#define NN 50000
#define NE 1600000
#define DD 32
static constexpr float Hstep = 0.1f;

// ---------------- static device scratch ----------------
__device__ int      g_is64;
__device__ int      g_deg[2][NN];
__device__ int      g_cur[2][NN];
__device__ int      g_rowptr[2][NN + 1];
__device__ __align__(16) unsigned g_colval[2][NE];   // low16 = col, high16 = fp16 val
__device__ float    g_dis[2][NN];
__device__ __align__(16) __half g_tmph[2][2 * NN * DD];  // ping-pong y buffers, both branches
__device__ __align__(128) float g_x[2 * NN * DD];
__device__ __align__(128) float g_ksum[2 * NN * DD];

// ---------------- edge readers (dtype-agnostic) ----------------
__device__ __forceinline__ int edge_src(const void* ei, int e, int is64) {
    if (is64) return (int)((const long long*)ei)[e];
    return ((const int*)ei)[e];
}
__device__ __forceinline__ int edge_dst(const void* ei, int e, int is64) {
    if (is64) return (int)((const long long*)ei)[NE + e];
    return ((const int*)ei)[NE + e];
}

// ---------------- setup: probe dtype + zero both degree arrays ----------------
__global__ void k_probe_zero(const int* __restrict__ w) {
    if (blockIdx.x == 0) {
        __shared__ int anynz;
        if (threadIdx.x == 0) anynz = 0;
        __syncthreads();
        if (w[2 * threadIdx.x + 1] != 0) atomicOr(&anynz, 1);
        __syncthreads();
        if (threadIdx.x == 0) g_is64 = (anynz == 0) ? 1 : 0;
    }
    int i = blockIdx.x * blockDim.x + threadIdx.x;
    int stride = gridDim.x * blockDim.x;
    for (; i < 2 * NN; i += stride) ((int*)g_deg)[i] = 0;
}

// both branches: blocks [0,H) -> pos, [H,2H) -> neg
__global__ void k_hist(const void* __restrict__ epos, const void* __restrict__ eneg) {
    const int H = gridDim.x >> 1;
    const int br = blockIdx.x >= H;
    const void* ei = br ? eneg : epos;
    const int bb = blockIdx.x - br * H;
    const int is64 = g_is64;
    int stride = H * blockDim.x;
    for (int e = bb * blockDim.x + threadIdx.x; e < NE; e += stride)
        atomicAdd(&g_deg[br][edge_dst(ei, e, is64)], 1);
}

// block b = branch b: dis + exclusive scan -> rowptr, cur
__global__ void k_scan_dis() {
    const int b = blockIdx.x;
    __shared__ int sm[1024];
    const int tid = threadIdx.x;
    const int CH = (NN + 1023) / 1024;  // 49
    int base = tid * CH;
    int s = 0;
    for (int i = 0; i < CH; i++) {
        int idx = base + i;
        if (idx < NN) {
            int d = g_deg[b][idx];
            g_dis[b][idx] = rsqrtf((float)d + 1.0f);
            s += d;
        }
    }
    sm[tid] = s;
    __syncthreads();
    for (int off = 1; off < 1024; off <<= 1) {
        int v = (tid >= off) ? sm[tid - off] : 0;
        __syncthreads();
        sm[tid] += v;
        __syncthreads();
    }
    int run = (tid == 0) ? 0 : sm[tid - 1];
    for (int i = 0; i < CH; i++) {
        int idx = base + i;
        if (idx < NN) {
            g_rowptr[b][idx] = run;
            g_cur[b][idx] = run;
            run += g_deg[b][idx];
        }
    }
    if (tid == 1023) g_rowptr[b][NN] = sm[1023];
}

// blocks [0,EB): scatter pos; [EB,2EB): scatter neg; rest: init x / tin
__global__ void __launch_bounds__(256) k_scatter_init(
    const void* __restrict__ epos, const void* __restrict__ eneg,
    const float* __restrict__ x0, int EB) {
    if (blockIdx.x < 2 * EB) {
        const int br = blockIdx.x >= EB;
        const void* ei = br ? eneg : epos;
        const int bb = blockIdx.x - br * EB;
        const int is64 = g_is64;
        int stride = EB * blockDim.x;
        for (int e = bb * blockDim.x + threadIdx.x; e < NE; e += stride) {
            int s = edge_src(ei, e, is64);
            int d = edge_dst(ei, e, is64);
            int p = atomicAdd(&g_cur[br][d], 1);
            __half hv = __float2half(g_dis[br][s] * g_dis[br][d]);
            g_colval[br][p] = (unsigned)s | ((unsigned)__half_as_ushort(hv) << 16);
        }
    } else {
        int i = (blockIdx.x - 2 * EB) * blockDim.x + threadIdx.x;
        int stride = (gridDim.x - 2 * EB) * blockDim.x;
        for (; i < 2 * NN * DD; i += stride) {
            float v = x0[i >= NN * DD ? i - NN * DD : i];
            g_x[i] = v;
            g_tmph[0][i] = __float2half(v);
        }
    }
}

// ---------------- fused RK4 stage, both branches, deferred @W ----------------
// Gather raw y (fp16): z = sum v*y_src + selfnorm*y_r; u = z @ W;
// k = relu(u + b)*gate; RK4 update scalar-per-lane; store y' (fp16) to tout.
template <int STAGE>
__global__ void __launch_bounds__(256) k_stage(
    int pin,
    const float* __restrict__ Wp, const float* __restrict__ bp, const float* __restrict__ wtp,
    const float* __restrict__ Wn, const float* __restrict__ bn, const float* __restrict__ wtn,
    float t, float* __restrict__ xout) {
    const int H = gridDim.x >> 1;
    const int br = blockIdx.x >= H;
    const float* __restrict__ W = br ? Wn : Wp;
    const float* __restrict__ bvec = br ? bn : bp;
    const float* __restrict__ wt = br ? wtn : wtp;
    const unsigned* __restrict__ colval = g_colval[br];
    const int* __restrict__ rowptr = g_rowptr[br];
    const float* __restrict__ dis = g_dis[br];
    const size_t boff = (size_t)br * NN * DD;
    const uint2* __restrict__ tin_v = (const uint2*)(g_tmph[pin]) + (size_t)br * NN * 8;
    __half* __restrict__ tout = g_tmph[pin ^ 1] + boff;
    const float* __restrict__ xbase = g_x + boff;
    float* __restrict__ xw = g_x + boff;
    float* __restrict__ ksb = g_ksum + boff;

    __shared__ float Wt[DD * 36];        // transposed W, row stride 36 floats
    __shared__ float zbuf[8][DD];
    {
        int tid = threadIdx.x;
        for (int idx = tid; idx < DD * DD; idx += 256) {
            int d = idx >> 5, l = idx & 31;
            Wt[l * 36 + d] = W[idx];
        }
    }
    __syncthreads();

    const int lane = threadIdx.x & 31;
    const int wid = threadIdx.x >> 5;
    const int li = lane & 7;
    const int g = lane >> 3;

    const float bb = __ldg(&bvec[lane]);
    const float gate = 1.0f / (1.0f + __expf(-t * __ldg(&wt[lane])));

    int warpLocal = (blockIdx.x - br * H) * 8 + wid;
    const int nwarps = H * 8;

    for (int r = warpLocal; r < NN; r += nwarps) {
        const int st = rowptr[r];
        const int en = rowptr[r + 1];
        float4 acc = make_float4(0.f, 0.f, 0.f, 0.f);

        // peel to 4-alignment (group g takes edge st+g)
        int pre = en - st;
        if (pre > ((4 - (st & 3)) & 3)) pre = (4 - (st & 3)) & 3;
        if (g < pre) {
            unsigned cv = __ldg(&colval[st + g]);
            float v = __half2float(__ushort_as_half((unsigned short)(cv >> 16)));
            union { uint2 u; __half2 h[2]; } rw;
            rw.u = __ldg(&tin_v[(size_t)(cv & 0xFFFFu) * 8 + li]);
            float2 a01 = __half22float2(rw.h[0]);
            float2 a23 = __half22float2(rw.h[1]);
            acc.x += v * a01.x; acc.y += v * a01.y;
            acc.z += v * a23.x; acc.w += v * a23.y;
        }
        int e = st + pre;
        // batch-16: group g loads colval[e+4g..e+4g+3] as one uint4, 4 gathers
        for (; e + 16 <= en; e += 16) {
            const uint4 cv = __ldg((const uint4*)&colval[e + 4 * g]);
            union { uint2 u; __half2 h[2]; } r0, r1, r2, r3;
            r0.u = __ldg(&tin_v[(size_t)(cv.x & 0xFFFFu) * 8 + li]);
            r1.u = __ldg(&tin_v[(size_t)(cv.y & 0xFFFFu) * 8 + li]);
            r2.u = __ldg(&tin_v[(size_t)(cv.z & 0xFFFFu) * 8 + li]);
            r3.u = __ldg(&tin_v[(size_t)(cv.w & 0xFFFFu) * 8 + li]);
            float v; float2 a;
            v = __half2float(__ushort_as_half((unsigned short)(cv.x >> 16)));
            a = __half22float2(r0.h[0]); acc.x += v * a.x; acc.y += v * a.y;
            a = __half22float2(r0.h[1]); acc.z += v * a.x; acc.w += v * a.y;
            v = __half2float(__ushort_as_half((unsigned short)(cv.y >> 16)));
            a = __half22float2(r1.h[0]); acc.x += v * a.x; acc.y += v * a.y;
            a = __half22float2(r1.h[1]); acc.z += v * a.x; acc.w += v * a.y;
            v = __half2float(__ushort_as_half((unsigned short)(cv.z >> 16)));
            a = __half22float2(r2.h[0]); acc.x += v * a.x; acc.y += v * a.y;
            a = __half22float2(r2.h[1]); acc.z += v * a.x; acc.w += v * a.y;
            v = __half2float(__ushort_as_half((unsigned short)(cv.w >> 16)));
            a = __half22float2(r3.h[0]); acc.x += v * a.x; acc.y += v * a.y;
            a = __half22float2(r3.h[1]); acc.z += v * a.x; acc.w += v * a.y;
        }
        // remainder: group g takes every 4th
        for (int ee = e + g; ee < en; ee += 4) {
            unsigned cv = __ldg(&colval[ee]);
            float v = __half2float(__ushort_as_half((unsigned short)(cv >> 16)));
            union { uint2 u; __half2 h[2]; } rw;
            rw.u = __ldg(&tin_v[(size_t)(cv & 0xFFFFu) * 8 + li]);
            float2 a01 = __half22float2(rw.h[0]);
            float2 a23 = __half22float2(rw.h[1]);
            acc.x += v * a01.x; acc.y += v * a01.y;
            acc.z += v * a23.x; acc.w += v * a23.y;
        }
        // combine 4 group partials (lanes with equal li)
#pragma unroll
        for (int off = 8; off < 32; off <<= 1) {
            acc.x += __shfl_xor_sync(0xffffffffu, acc.x, off);
            acc.y += __shfl_xor_sync(0xffffffffu, acc.y, off);
            acc.z += __shfl_xor_sync(0xffffffffu, acc.z, off);
            acc.w += __shfl_xor_sync(0xffffffffu, acc.w, off);
        }
        // self term (all lanes compute identically)
        {
            const float dn = dis[r];
            const float sn = dn * dn;
            union { uint2 u; __half2 h[2]; } sw;
            sw.u = __ldg(&tin_v[(size_t)r * 8 + li]);
            float2 s01 = __half22float2(sw.h[0]);
            float2 s23 = __half22float2(sw.h[1]);
            acc.x += sn * s01.x; acc.y += sn * s01.y;
            acc.z += sn * s23.x; acc.w += sn * s23.y;
        }
        // z -> smem (group 0), then per-lane u = z @ W[:,lane]
        if (g == 0) ((float4*)zbuf[wid])[li] = acc;
        __syncwarp();
        float u = 0.f;
        {
            const float4* zp = (const float4*)zbuf[wid];
            const float4* wp = (const float4*)&Wt[lane * 36];
#pragma unroll
            for (int q = 0; q < 8; q++) {
                const float4 zq = zp[q];
                const float4 wq = wp[q];
                u += zq.x * wq.x + zq.y * wq.y + zq.z * wq.z + zq.w * wq.w;
            }
        }
        __syncwarp();

        const float k = fmaxf(u + bb, 0.f) * gate;
        const int idx = r * 32 + lane;
        const float xv = xbase[idx];
        float y;
        if (STAGE == 1) {
            ksb[idx] = k;
            y = xv + 0.5f * Hstep * k;
        } else if (STAGE == 2) {
            ksb[idx] += 2.f * k;
            y = xv + 0.5f * Hstep * k;
        } else if (STAGE == 3) {
            ksb[idx] += 2.f * k;
            y = xv + Hstep * k;
        } else {
            y = xv + (Hstep / 6.f) * (ksb[idx] + k);
            if (xout) xout[boff + idx] = y;
            else      xw[idx] = y;
        }
        tout[idx] = __float2half(y);
    }
}

// ---------------- host ----------------
extern "C" void kernel_launch(void* const* d_in, const int* in_sizes, int n_in,
                              void* d_out, int out_size) {
    const float* x0 = (const float*)d_in[0];
    const void* epos = d_in[1];
    const void* eneg = d_in[2];
    const float* Wp = (const float*)d_in[3];
    const float* bp = (const float*)d_in[4];
    const float* wtp = (const float*)d_in[5];
    const float* Wn = (const float*)d_in[6];
    const float* bn = (const float*)d_in[7];
    const float* wtn = (const float*)d_in[8];
    float* out = (float*)d_out;

    const int STAGE_BLOCKS = 592;  // 296 per branch
    const int EB = 1184;

    k_probe_zero<<<196, 256>>>((const int*)epos);
    k_hist<<<2 * EB, 256>>>(epos, eneg);
    k_scan_dis<<<2, 1024>>>();
    k_scatter_init<<<2 * EB + 296, 256>>>(epos, eneg, x0, EB);

    int pin = 0;
    for (int step = 0; step < 10; step++) {
        float t = step * Hstep;
        k_stage<1><<<STAGE_BLOCKS, 256>>>(pin, Wp, bp, wtp, Wn, bn, wtn, t, nullptr);
        pin ^= 1;
        k_stage<2><<<STAGE_BLOCKS, 256>>>(pin, Wp, bp, wtp, Wn, bn, wtn, t + 0.5f * Hstep, nullptr);
        pin ^= 1;
        k_stage<3><<<STAGE_BLOCKS, 256>>>(pin, Wp, bp, wtp, Wn, bn, wtn, t + 0.5f * Hstep, nullptr);
        pin ^= 1;
        float* xo = (step == 9) ? out : nullptr;
        k_stage<4><<<STAGE_BLOCKS, 256>>>(pin, Wp, bp, wtp, Wn, bn, wtn, t + Hstep, xo);
        pin ^= 1;
    }
}